// round 1
// baseline (speedup 1.0000x reference)
#include <cuda_runtime.h>
#include <math.h>

#define TT 512
#define BB 128
#define II 256
#define HH 1024
#define G4 (4 * HH)

// ---------------- scratch (allocation-free contract: __device__ globals) -----
__device__ float g_xproj[(size_t)TT * BB * G4];   // 1 GiB: x @ W_ih^T + b_ih + b_hh
__device__ float g_c[BB * HH];                    // running cell state

// ---------------------------------------------------------------------------
// init: copy c0 into scratch (must happen every launch for determinism)
// ---------------------------------------------------------------------------
__global__ void init_c_kernel(const float* __restrict__ c0) {
    int idx = blockIdx.x * blockDim.x + threadIdx.x;
    if (idx < BB * HH) g_c[idx] = c0[idx];
}

// ---------------------------------------------------------------------------
// x_proj GEMM: C[M=65536, N=4096] = A[M,256] * W_ih[N,256]^T + (b_ih+b_hh)
// BM=64, BN=64, BK=32, 256 threads, 4x4 per thread, transposed smem tiles
// ---------------------------------------------------------------------------
__global__ __launch_bounds__(256) void xproj_kernel(
    const float* __restrict__ inp,    // [65536, 256]
    const float* __restrict__ W_ih,   // [4096, 256]
    const float* __restrict__ b_ih,
    const float* __restrict__ b_hh)
{
    __shared__ float As[32][64];   // [k][m]
    __shared__ float Bs[32][64];   // [k][n]

    const int tid = threadIdx.x;
    const int tx = tid & 15;       // n group
    const int ty = tid >> 4;       // m group
    const int n0 = blockIdx.x * 64;
    const int m0 = blockIdx.y * 64;

    float acc[4][4];
#pragma unroll
    for (int r = 0; r < 4; r++)
#pragma unroll
        for (int c = 0; c < 4; c++) acc[r][c] = 0.f;

    for (int k0 = 0; k0 < II; k0 += 32) {
#pragma unroll
        for (int v = 0; v < 2; v++) {
            int e = tid + 256 * v;          // 0..511
            int row = e >> 3;               // 0..63
            int kk = (e & 7) * 4;
            float4 a = *(const float4*)(inp + (size_t)(m0 + row) * II + k0 + kk);
            As[kk + 0][row] = a.x; As[kk + 1][row] = a.y;
            As[kk + 2][row] = a.z; As[kk + 3][row] = a.w;
            float4 b = *(const float4*)(W_ih + (size_t)(n0 + row) * II + k0 + kk);
            Bs[kk + 0][row] = b.x; Bs[kk + 1][row] = b.y;
            Bs[kk + 2][row] = b.z; Bs[kk + 3][row] = b.w;
        }
        __syncthreads();
#pragma unroll
        for (int kk = 0; kk < 32; kk++) {
            float4 av = *(const float4*)(&As[kk][ty * 4]);
            float4 bv = *(const float4*)(&Bs[kk][tx * 4]);
            float a4[4] = {av.x, av.y, av.z, av.w};
            float b4[4] = {bv.x, bv.y, bv.z, bv.w};
#pragma unroll
            for (int r = 0; r < 4; r++)
#pragma unroll
                for (int c = 0; c < 4; c++) acc[r][c] += a4[r] * b4[c];
        }
        __syncthreads();
    }

#pragma unroll
    for (int c = 0; c < 4; c++) {
        int n = n0 + tx * 4 + c;
        float bias = b_ih[n] + b_hh[n];
#pragma unroll
        for (int r = 0; r < 4; r++) {
            int m = m0 + ty * 4 + r;
            g_xproj[(size_t)m * G4 + n] = acc[r][c] + bias;
        }
    }
}

// ---------------------------------------------------------------------------
// one LSTM timestep, fully fused:
//   gates[128, 4096] = x_proj[t] + h_prev @ W_hh^T   then cell update
// Grid: (jb=32 h-col tiles of 32, mb=8 batch tiles of 16), 256 threads.
// Each thread owns one h-column (lane) and 2 batch rows, and accumulates all
// 4 gates for that (b, hcol) so the cell update happens in-register.
// ---------------------------------------------------------------------------
__device__ __forceinline__ float sigmoidf_(float x) {
    return 1.0f / (1.0f + expf(-x));
}

__global__ __launch_bounds__(256) void lstm_step_kernel(
    const float* __restrict__ hprev,  // [128, 1024]
    const float* __restrict__ W_hh,   // [4096, 1024]
    float* __restrict__ out,          // full output buffer
    int t)
{
    __shared__ float As[16][36];        // h tile [m][k], padded
    __shared__ float Ws[4][32][36];     // weight tile [gate][hcol][k], padded

    const int tid  = threadIdx.x;
    const int lane = tid & 31;          // hcol within tile
    const int mgrp = tid >> 5;          // 0..7
    const int jb = blockIdx.x;          // 0..31
    const int mb = blockIdx.y;          // 0..7
    const int m0 = mb * 16;
    const int hc = jb * 32 + lane;      // this thread's h column

    float acc[2][4];
#pragma unroll
    for (int r = 0; r < 2; r++)
#pragma unroll
        for (int g = 0; g < 4; g++) acc[r][g] = 0.f;

    for (int k0 = 0; k0 < HH; k0 += 32) {
        // h tile: 16 rows x 32 k = 512 floats -> first 128 threads, 1 float4 each
        if (tid < 128) {
            int row = tid >> 3;
            int kk = (tid & 7) * 4;
            *(float4*)(&As[row][kk]) =
                *(const float4*)(hprev + (size_t)(m0 + row) * HH + k0 + kk);
        }
        // W tile: 128 rows x 32 k = 4096 floats -> 4 float4 each
#pragma unroll
        for (int v = 0; v < 4; v++) {
            int e = tid + 256 * v;          // 0..1023
            int row = e >> 3;               // 0..127
            int kk = (e & 7) * 4;
            int g = row >> 5, hcl = row & 31;
            *(float4*)(&Ws[g][hcl][kk]) =
                *(const float4*)(W_hh + (size_t)(g * HH + jb * 32 + hcl) * HH + k0 + kk);
        }
        __syncthreads();
#pragma unroll
        for (int kk = 0; kk < 32; kk += 4) {
            float4 a[2], w[4];
#pragma unroll
            for (int r = 0; r < 2; r++)
                a[r] = *(const float4*)(&As[mgrp * 2 + r][kk]);
#pragma unroll
            for (int g = 0; g < 4; g++)
                w[g] = *(const float4*)(&Ws[g][lane][kk]);
#pragma unroll
            for (int r = 0; r < 2; r++) {
#pragma unroll
                for (int g = 0; g < 4; g++) {
                    acc[r][g] += a[r].x * w[g].x;
                    acc[r][g] += a[r].y * w[g].y;
                    acc[r][g] += a[r].z * w[g].z;
                    acc[r][g] += a[r].w * w[g].w;
                }
            }
        }
        __syncthreads();
    }

    // fused LSTM cell epilogue
    const size_t OUT_H = (size_t)TT * BB * HH;
#pragma unroll
    for (int r = 0; r < 2; r++) {
        int b = m0 + mgrp * 2 + r;
        const float* xp = g_xproj + ((size_t)t * BB + b) * G4;
        float ig = sigmoidf_(acc[r][0] + xp[0 * HH + hc]);
        float fg = sigmoidf_(acc[r][1] + xp[1 * HH + hc]);
        float gg = tanhf   (acc[r][2] + xp[2 * HH + hc]);
        float og = sigmoidf_(acc[r][3] + xp[3 * HH + hc]);

        size_t cidx = (size_t)b * HH + hc;
        float c_new = fg * g_c[cidx] + ig * gg;
        g_c[cidx] = c_new;
        float h_new = og * tanhf(c_new);

        out[(size_t)t * BB * HH + cidx] = h_new;
        if (t == TT - 1) {
            out[OUT_H + cidx] = h_new;                      // h_final
            out[OUT_H + (size_t)BB * HH + cidx] = c_new;    // c_final
        }
    }
}

// ---------------------------------------------------------------------------
extern "C" void kernel_launch(void* const* d_in, const int* in_sizes, int n_in,
                              void* d_out, int out_size) {
    const float* inputs = (const float*)d_in[0];  // [512,128,256]
    const float* h0     = (const float*)d_in[1];  // [128,1024]
    const float* c0     = (const float*)d_in[2];  // [128,1024]
    const float* W_ih   = (const float*)d_in[3];  // [4096,256]
    const float* W_hh   = (const float*)d_in[4];  // [4096,1024]
    const float* b_ih   = (const float*)d_in[5];  // [4096]
    const float* b_hh   = (const float*)d_in[6];  // [4096]
    float* out = (float*)d_out;

    // c scratch init (every call: graph replays must be deterministic)
    init_c_kernel<<<(BB * HH + 255) / 256, 256>>>(c0);

    // big input-projection GEMM: [65536, 4096]
    {
        dim3 grid(G4 / 64, (TT * BB) / 64);
        xproj_kernel<<<grid, 256>>>(inputs, W_ih, b_ih, b_hh);
    }

    // sequential scan: 512 fused step kernels
    dim3 sgrid(32, 8);
    for (int t = 0; t < TT; t++) {
        const float* hprev = (t == 0) ? h0 : (out + (size_t)(t - 1) * BB * HH);
        lstm_step_kernel<<<sgrid, 256>>>(hprev, W_hh, out, t);
    }
}